// round 9
// baseline (speedup 1.0000x reference)
#include <cuda_runtime.h>

typedef unsigned long long u64;

#define BN 16
#define CN 4
#define HN 512
#define WN 512
#define HID 32
#define TX 32
#define TY 32
#define RAD 3
#define RH (TY + 2*RAD)      /* 38 rows of horizontal sums */
#define NCP (TX/2)           /* 16 column pairs */

/* ---------------- f32x2 helpers (sm_100+ packed fp32) ---------------- */
__device__ __forceinline__ u64 pk(float lo, float hi){ u64 r; asm("mov.b64 %0,{%1,%2};":"=l"(r):"f"(lo),"f"(hi)); return r; }
__device__ __forceinline__ void upk(u64 v,float&lo,float&hi){ asm("mov.b64 {%0,%1},%2;":"=f"(lo),"=f"(hi):"l"(v)); }
__device__ __forceinline__ u64 dup2(float x){ u64 r; asm("mov.b64 %0,{%1,%1};":"=l"(r):"f"(x)); return r; }
__device__ __forceinline__ u64 ffma2(u64 a,u64 b,u64 c){ u64 d; asm("fma.rn.f32x2 %0,%1,%2,%3;":"=l"(d):"l"(a),"l"(b),"l"(c)); return d; }
__device__ __forceinline__ u64 fadd2(u64 a,u64 b){ u64 d; asm("add.rn.f32x2 %0,%1,%2;":"=l"(d):"l"(a),"l"(b)); return d; }
__device__ __forceinline__ u64 fmul2(u64 a,u64 b){ u64 d; asm("mul.rn.f32x2 %0,%1,%2;":"=l"(d):"l"(a),"l"(b)); return d; }
__device__ __forceinline__ float rcpf(float x){ float r; asm("rcp.approx.ftz.f32 %0,%1;":"=f"(r):"f"(x)); return r; }
__device__ __forceinline__ float ex2f(float x){ float r; asm("ex2.approx.ftz.f32 %0,%1;":"=f"(r):"f"(x)); return r; }

#define SGNM 0x8000000080000000ULL

/* tanh-form gelu on a packed pair:
   g = h - h*r,  r = 1/(1 + exp(2t)),  t = sqrt(2/pi)*(h + 0.044715 h^3)
   exponent computed directly in base-2: e2t = ex2(h*(C1 + C2*h^2)),
   C1 = 2*log2(e)*0.7978845608, C2 = C1*0.044715.
   Saturates cleanly: +inf -> r=0 -> g=h ; 0 -> r=1 -> g=0. */
__device__ __forceinline__ u64 gelu2(u64 h){
  u64 h2   = fmul2(h, h);
  u64 s    = ffma2(h2, dup2(0.10294456f), dup2(2.3022077f));
  u64 targ = fmul2(h, s);
  float t0,t1; upk(targ,t0,t1);
  u64 E    = pk(ex2f(t0), ex2f(t1));
  u64 den  = fadd2(E, dup2(1.0f));
  float d0,d1; upk(den,d0,d1);
  u64 r    = pk(rcpf(d0), rcpf(d1));
  u64 m    = fmul2(h, r);
  return fadd2(h, m ^ SGNM);     /* h - h*r */
}

__device__ __forceinline__ int refl(int i, int n){
  if (i < 0) i = -i;
  if (i >= n) i = 2*n - 2 - i;
  return i;
}

__global__ void __launch_bounds__(256,2)
lee_kernel(const float* __restrict__ x, const float* __restrict__ W1,
           const float* __restrict__ b1, const float* __restrict__ W2,
           const float* __restrict__ b2, float* __restrict__ out)
{
  /* horiz 7-sums (stage 1) -> converted IN PLACE to full 7x7 sums (stage 1.5) */
  __shared__ __align__(16) u64 hsp[CN][RH][NCP];
  __shared__ __align__(16) u64 hqp[CN][RH][NCP];
  __shared__ __align__(16) u64 w1d[HID][16];       /* dup-packed weights */
  __shared__ __align__(16) u64 w2d[HID][CN];
  __shared__ __align__(16) u64 b1d[HID];
  __shared__ __align__(16) u64 b2d[CN];

  const int tid = threadIdx.x;
  const int x0 = blockIdx.x * TX;
  const int y0 = blockIdx.y * TY;
  const int b  = blockIdx.z;
  const float* xb = x + (size_t)b * CN * HN * WN;

  /* ---- weights -> dup-packed shared ---- */
  for (int i = tid; i < HID*16; i += 256){ float v = W1[i]; w1d[i>>4][i&15] = pk(v,v); }
  if (tid < HID*CN){ int k = tid >> 2, c = tid & 3; float v = W2[c*HID + k]; w2d[k][c] = pk(v,v); }
  if (tid < HID){ float v = b1[tid]; b1d[tid] = pk(v,v); }
  if (tid < CN){ float v = b2[tid]; b2d[tid] = pk(v,v); }

  /* ---- stage 1: horizontal 7-window running sums, 4 columns per item ---- */
  const bool ix = (x0 >= RAD) && (x0 + TX + RAD <= WN);
  for (int t = tid; t < CN*RH*8; t += 256){
    int c = t & 3;
    int g = (t >> 2) & 7;            /* group of 4 output columns */
    int r = t >> 5;                  /* 0..37 */
    int gy = refl(y0 - RAD + r, HN);
    const float* row = xb + ((size_t)c*HN + gy) * WN;
    int base = x0 + 4*g - RAD;
    float v[10];
    if (ix){
      const float4* p = (const float4*)(row + base - 1);   /* 16B aligned */
      float4 f0 = __ldg(p), f1 = __ldg(p+1), f2 = __ldg(p+2);
      v[0]=f0.y; v[1]=f0.z; v[2]=f0.w; v[3]=f1.x; v[4]=f1.y;
      v[5]=f1.z; v[6]=f1.w; v[7]=f2.x; v[8]=f2.y; v[9]=f2.z;
    } else {
      #pragma unroll
      for (int d = 0; d < 10; d++) v[d] = __ldg(row + refl(base + d, WN));
    }
    float s0 = ((v[0]+v[1])+(v[2]+v[3])) + ((v[4]+v[5])+v[6]);
    float s1 = s0 + (v[7]-v[0]);
    float s2 = s1 + (v[8]-v[1]);
    float s3 = s2 + (v[9]-v[2]);
    float w[10];
    #pragma unroll
    for (int d = 0; d < 10; d++) w[d] = v[d]*v[d];
    float q0 = ((w[0]+w[1])+(w[2]+w[3])) + ((w[4]+w[5])+w[6]);
    float q1 = q0 + (w[7]-w[0]);
    float q2 = q1 + (w[8]-w[1]);
    float q3 = q2 + (w[9]-w[2]);
    hsp[c][r][2*g]   = pk(s0,s1);
    hsp[c][r][2*g+1] = pk(s2,s3);
    hqp[c][r][2*g]   = pk(q0,q1);
    hqp[c][r][2*g+1] = pk(q2,q3);
  }
  __syncthreads();

  /* ---- stage 1.5: vertical 7-sums IN PLACE (regs-first, barrier, write) ---- */
  {
    int c  = tid & 3;
    int px = (tid >> 2) & 15;
    int qy = tid >> 6;               /* 0..3 -> rows 8qy..8qy+7 */
    u64 rs[14], rq[14];
    #pragma unroll
    for (int j = 0; j < 14; j++){ rs[j] = hsp[c][8*qy + j][px]; rq[j] = hqp[c][8*qy + j][px]; }
    __syncthreads();                 /* everyone captured inputs before any write */
    u64 s = fadd2(fadd2(fadd2(rs[0],rs[1]), fadd2(rs[2],rs[3])), fadd2(fadd2(rs[4],rs[5]), rs[6]));
    u64 q = fadd2(fadd2(fadd2(rq[0],rq[1]), fadd2(rq[2],rq[3])), fadd2(fadd2(rq[4],rq[5]), rq[6]));
    hsp[c][8*qy][px] = s;
    hqp[c][8*qy][px] = q;
    #pragma unroll
    for (int i = 1; i < 8; i++){
      s = fadd2(s, fadd2(rs[i+6], rs[i-1] ^ SGNM));
      q = fadd2(q, fadd2(rq[i+6], rq[i-1] ^ SGNM));
      hsp[c][8*qy + i][px] = s;
      hqp[c][8*qy + i][px] = q;
    }
  }
  __syncthreads();

  /* ---- stage 2: two vertically-adjacent pixel-pairs per thread + MLP ---- */
  const int tpx = tid & (NCP-1);
  const int ty2 = tid >> 4;          /* 0..15 -> rows 2*ty2, 2*ty2+1 */
  const int yA = 2*ty2, yB = 2*ty2 + 1;
  const int col0 = x0 + 2*tpx;
  const u64 INV49 = dup2(1.0f/49.0f);

  u64 featA[16], featB[16];
  #pragma unroll
  for (int c = 0; c < CN; c++){
    u64 sA = hsp[c][yA][tpx], qA = hqp[c][yA][tpx];
    u64 sB = hsp[c][yB][tpx], qB = hqp[c][yB][tpx];
    u64 meanA = fmul2(sA, INV49), msqA = fmul2(qA, INV49);
    u64 meanB = fmul2(sB, INV49), msqB = fmul2(qB, INV49);
    u64 varA = ffma2(meanA, meanA ^ SGNM, msqA);
    u64 varB = ffma2(meanB, meanB ^ SGNM, msqB);
    { float a0,a1; upk(varA,a0,a1); varA = pk(fmaxf(a0,0.f), fmaxf(a1,0.f)); }
    { float a0,a1; upk(varB,a0,a1); varB = pk(fmaxf(a0,0.f), fmaxf(a1,0.f)); }
    featA[c]    = *(const u64*)(xb + ((size_t)c*HN + y0 + yA)*WN + col0);
    featB[c]    = *(const u64*)(xb + ((size_t)c*HN + y0 + yB)*WN + col0);
    featA[4+c]  = meanA;  featB[4+c]  = meanB;
    featA[8+c]  = varA;   featB[8+c]  = varB;
    featA[12+c] = msqA;   featB[12+c] = msqB;
  }

  u64 accA[CN], accB[CN];
  #pragma unroll
  for (int c = 0; c < CN; c++){
    accA[c] = fadd2(featA[c], b2d[c]);
    accB[c] = fadd2(featB[c], b2d[c]);
  }

  #pragma unroll 2
  for (int kk = 0; kk < HID; kk += 2){
    u64 aA0 = b1d[kk],   aB0 = b1d[kk];
    u64 aA1 = b1d[kk+1], aB1 = b1d[kk+1];
    const ulonglong2* w0  = (const ulonglong2*)&w1d[kk][0];
    const ulonglong2* w1r = (const ulonglong2*)&w1d[kk+1][0];
    #pragma unroll
    for (int j = 0; j < 8; j++){
      ulonglong2 wa = w0[j], wb = w1r[j];
      aA0 = ffma2(featA[2*j],   wa.x, aA0);
      aB0 = ffma2(featB[2*j],   wa.x, aB0);
      aA1 = ffma2(featA[2*j],   wb.x, aA1);
      aB1 = ffma2(featB[2*j],   wb.x, aB1);
      aA0 = ffma2(featA[2*j+1], wa.y, aA0);
      aB0 = ffma2(featB[2*j+1], wa.y, aB0);
      aA1 = ffma2(featA[2*j+1], wb.y, aA1);
      aB1 = ffma2(featB[2*j+1], wb.y, aB1);
    }
    u64 gA0 = gelu2(aA0), gB0 = gelu2(aB0);
    u64 gA1 = gelu2(aA1), gB1 = gelu2(aB1);
    const ulonglong2* w2a = (const ulonglong2*)&w2d[kk][0];
    const ulonglong2* w2b = (const ulonglong2*)&w2d[kk+1][0];
    ulonglong2 p0 = w2a[0], p1 = w2a[1], p2 = w2b[0], p3 = w2b[1];
    accA[0] = ffma2(gA0, p0.x, accA[0]);  accA[0] = ffma2(gA1, p2.x, accA[0]);
    accB[0] = ffma2(gB0, p0.x, accB[0]);  accB[0] = ffma2(gB1, p2.x, accB[0]);
    accA[1] = ffma2(gA0, p0.y, accA[1]);  accA[1] = ffma2(gA1, p2.y, accA[1]);
    accB[1] = ffma2(gB0, p0.y, accB[1]);  accB[1] = ffma2(gB1, p2.y, accB[1]);
    accA[2] = ffma2(gA0, p1.x, accA[2]);  accA[2] = ffma2(gA1, p3.x, accA[2]);
    accB[2] = ffma2(gB0, p1.x, accB[2]);  accB[2] = ffma2(gB1, p3.x, accB[2]);
    accA[3] = ffma2(gA0, p1.y, accA[3]);  accA[3] = ffma2(gA1, p3.y, accA[3]);
    accB[3] = ffma2(gB0, p1.y, accB[3]);  accB[3] = ffma2(gB1, p3.y, accB[3]);
  }

  float* ob = out + (size_t)b * CN*HN*WN;
  #pragma unroll
  for (int c = 0; c < CN; c++){
    *(u64*)(ob + ((size_t)c*HN + y0 + yA)*WN + col0) = accA[c];
    *(u64*)(ob + ((size_t)c*HN + y0 + yB)*WN + col0) = accB[c];
  }
}

extern "C" void kernel_launch(void* const* d_in, const int* in_sizes, int n_in,
                              void* d_out, int out_size)
{
  const float *x=0, *W1=0, *b1=0, *W2=0, *b2=0;
  for (int i = 0; i < n_in; i++){
    switch (in_sizes[i]){
      case BN*CN*HN*WN: x  = (const float*)d_in[i]; break;
      case HID*4*CN:    W1 = (const float*)d_in[i]; break;
      case HID:         b1 = (const float*)d_in[i]; break;
      case CN*HID:      W2 = (const float*)d_in[i]; break;
      case CN:          b2 = (const float*)d_in[i]; break;
      default: break;
    }
  }
  dim3 grid(WN/TX, HN/TY, BN);   /* 16 x 16 x 16 */
  lee_kernel<<<grid, 256>>>(x, W1, b1, W2, b2, (float*)d_out);
}

// round 13
// speedup vs baseline: 1.1867x; 1.1867x over previous
#include <cuda_runtime.h>
#include <cstdint>
typedef unsigned long long u64;
typedef unsigned int u32;

#define BN 16
#define CN 4
#define HN 512
#define WN 512
#define HID 32
#define TX 32
#define TY 32
#define RAD 3
#define RH 38
#define RPAD 36            /* padded floats per hsp/hqp row (18 u64) */

#define OFF_G  0           /* 8 warps x 16 rows x 36 floats = 18432 B */
#define OFF_HS 18432       /* 4*38*36*4 = 21888 B */
#define OFF_HQ 40320       /* 21888 B */
#define SMEM_TOTAL 62208

#define SGNM 0x8000000080000000ULL

/* ---------------- f32x2 helpers ---------------- */
__device__ __forceinline__ u64 pk(float lo, float hi){ u64 r; asm("mov.b64 %0,{%1,%2};":"=l"(r):"f"(lo),"f"(hi)); return r; }
__device__ __forceinline__ void upk(u64 v,float&lo,float&hi){ asm("mov.b64 {%0,%1},%2;":"=f"(lo),"=f"(hi):"l"(v)); }
__device__ __forceinline__ u64 dup2(float x){ u64 r; asm("mov.b64 %0,{%1,%1};":"=l"(r):"f"(x)); return r; }
__device__ __forceinline__ u64 ffma2(u64 a,u64 b,u64 c){ u64 d; asm("fma.rn.f32x2 %0,%1,%2,%3;":"=l"(d):"l"(a),"l"(b),"l"(c)); return d; }
__device__ __forceinline__ u64 fadd2(u64 a,u64 b){ u64 d; asm("add.rn.f32x2 %0,%1,%2;":"=l"(d):"l"(a),"l"(b)); return d; }
__device__ __forceinline__ u64 fmul2(u64 a,u64 b){ u64 d; asm("mul.rn.f32x2 %0,%1,%2;":"=l"(d):"l"(a),"l"(b)); return d; }
__device__ __forceinline__ float rcpf(float x){ float r; asm("rcp.approx.ftz.f32 %0,%1;":"=f"(r):"f"(x)); return r; }
__device__ __forceinline__ float ex2f(float x){ float r; asm("ex2.approx.ftz.f32 %0,%1;":"=f"(r):"f"(x)); return r; }

/* tanh-form gelu (validated R8, rel_err 1.6e-5) */
__device__ __forceinline__ u64 gelu2(u64 h){
  u64 h2 = fmul2(h, h);
  u64 s  = ffma2(h2, dup2(0.10294456f), dup2(2.3022077f));
  u64 tg = fmul2(h, s);
  float t0,t1; upk(tg,t0,t1);
  u64 E  = pk(ex2f(t0), ex2f(t1));
  u64 dn = fadd2(E, dup2(1.0f));
  float d0,d1; upk(dn,d0,d1);
  u64 r  = pk(rcpf(d0), rcpf(d1));
  u64 m  = fmul2(h, r);
  return fadd2(h, m ^ SGNM);
}
__device__ __forceinline__ int refl(int i, int n){ if (i<0) i=-i; if (i>=n) i=2*n-2-i; return i; }

/* tf32 convert (round-to-nearest) */
__device__ __forceinline__ u32 tf(float f){ u32 r; asm("cvt.rna.tf32.f32 %0, %1;":"=r"(r):"f"(f)); return r; }

/* m16n8k8 tf32 MMA, accumulate in place */
__device__ __forceinline__ void mma8(float* d, u32 a0, u32 a1, u32 a2, u32 a3, u32 b0, u32 b1){
  asm volatile(
    "mma.sync.aligned.m16n8k8.row.col.f32.tf32.tf32.f32 "
    "{%0,%1,%2,%3},{%4,%5,%6,%7},{%8,%9},{%0,%1,%2,%3};"
    : "+f"(d[0]),"+f"(d[1]),"+f"(d[2]),"+f"(d[3])
    : "r"(a0),"r"(a1),"r"(a2),"r"(a3),"r"(b0),"r"(b1));
}

__global__ void __launch_bounds__(256,2)
lee_kernel(const float* __restrict__ x, const float* __restrict__ W1,
           const float* __restrict__ b1, const float* __restrict__ W2,
           const float* __restrict__ b2, float* __restrict__ out)
{
  extern __shared__ __align__(16) char smem[];
  const int tid = threadIdx.x;
  const int w    = tid >> 5;          /* warp 0..7 */
  const int lane = tid & 31;
  const int gid  = lane >> 2;         /* 0..7 */
  const int tig  = lane & 3;          /* 0..3 */
  const int x0 = blockIdx.x * TX;
  const int y0 = blockIdx.y * TY;
  const int b  = blockIdx.z;
  const float* xb = x + (size_t)b * CN * HN * WN;

  /* ---- weight fragments -> registers (once) ---- */
  u32 w1f[2][4][2];
  #pragma unroll
  for (int kt = 0; kt < 2; kt++)
    #pragma unroll
    for (int nt = 0; nt < 4; nt++){
      w1f[kt][nt][0] = tf(__ldg(W1 + (nt*8 + gid)*16 + kt*8 + tig));
      w1f[kt][nt][1] = tf(__ldg(W1 + (nt*8 + gid)*16 + kt*8 + tig + 4));
    }
  u32 w2f[4][2];
  #pragma unroll
  for (int kt = 0; kt < 4; kt++){
    w2f[kt][0] = (gid < CN) ? tf(__ldg(W2 + gid*HID + kt*8 + tig))     : 0u;
    w2f[kt][1] = (gid < CN) ? tf(__ldg(W2 + gid*HID + kt*8 + tig + 4)) : 0u;
  }
  u64 b1p[4];
  #pragma unroll
  for (int nt = 0; nt < 4; nt++)
    b1p[nt] = pk(__ldg(b1 + nt*8 + 2*tig), __ldg(b1 + nt*8 + 2*tig + 1));
  float b2v0 = (tig < 2) ? __ldg(b2 + 2*tig)     : 0.0f;
  float b2v1 = (tig < 2) ? __ldg(b2 + 2*tig + 1) : 0.0f;

  u64* hsw = (u64*)(smem + OFF_HS);
  u64* hqw = (u64*)(smem + OFF_HQ);

  /* ---- stage 1: horizontal 7-window running sums (proven; rows padded to 36) ---- */
  const bool ixf = (x0 >= RAD) && (x0 + TX + RAD <= WN);
  for (int t = tid; t < CN*RH*8; t += 256){
    int c = t & 3, g = (t >> 2) & 7, r = t >> 5;
    int gy = refl(y0 - RAD + r, HN);
    const float* row = xb + ((size_t)c*HN + gy) * WN;
    int base = x0 + 4*g - RAD;
    float v[10];
    if (ixf){
      const float4* p = (const float4*)(row + base - 1);
      float4 f0 = __ldg(p), f1 = __ldg(p+1), f2 = __ldg(p+2);
      v[0]=f0.y; v[1]=f0.z; v[2]=f0.w; v[3]=f1.x; v[4]=f1.y;
      v[5]=f1.z; v[6]=f1.w; v[7]=f2.x; v[8]=f2.y; v[9]=f2.z;
    } else {
      #pragma unroll
      for (int d = 0; d < 10; d++) v[d] = __ldg(row + refl(base + d, WN));
    }
    float s0 = ((v[0]+v[1])+(v[2]+v[3])) + ((v[4]+v[5])+v[6]);
    float s1 = s0 + (v[7]-v[0]);
    float s2 = s1 + (v[8]-v[1]);
    float s3 = s2 + (v[9]-v[2]);
    float q[10];
    #pragma unroll
    for (int d = 0; d < 10; d++) q[d] = v[d]*v[d];
    float q0 = ((q[0]+q[1])+(q[2]+q[3])) + ((q[4]+q[5])+q[6]);
    float q1 = q0 + (q[7]-q[0]);
    float q2 = q1 + (q[8]-q[1]);
    float q3 = q2 + (q[9]-q[2]);
    int bi = (c*RH + r)*18 + 2*g;
    hsw[bi]   = pk(s0,s1);  hsw[bi+1] = pk(s2,s3);
    hqw[bi]   = pk(q0,q1);  hqw[bi+1] = pk(q2,q3);
  }
  __syncthreads();

  /* ---- stage 1.5: vertical 7-sums IN PLACE (proven) ---- */
  {
    int c  = tid & 3, px = (tid >> 2) & 15, qy = tid >> 6;
    u64 rs[14], rq[14];
    #pragma unroll
    for (int j = 0; j < 14; j++){
      rs[j] = hsw[(c*RH + 8*qy + j)*18 + px];
      rq[j] = hqw[(c*RH + 8*qy + j)*18 + px];
    }
    __syncthreads();
    u64 s = fadd2(fadd2(fadd2(rs[0],rs[1]), fadd2(rs[2],rs[3])), fadd2(fadd2(rs[4],rs[5]), rs[6]));
    u64 q = fadd2(fadd2(fadd2(rq[0],rq[1]), fadd2(rq[2],rq[3])), fadd2(fadd2(rq[4],rq[5]), rq[6]));
    hsw[(c*RH + 8*qy)*18 + px] = s;
    hqw[(c*RH + 8*qy)*18 + px] = q;
    #pragma unroll
    for (int i = 1; i < 8; i++){
      s = fadd2(s, fadd2(rs[i+6], rs[i-1] ^ SGNM));
      q = fadd2(q, fadd2(rq[i+6], rq[i-1] ^ SGNM));
      hsw[(c*RH + 8*qy + i)*18 + px] = s;
      hqw[(c*RH + 8*qy + i)*18 + px] = q;
    }
  }
  __syncthreads();

  /* ---- stage 2: warp-level tf32 MMA over 16-px groups ---- */
  const float* hsf = (const float*)(smem + OFF_HS);
  const float* hqf = (const float*)(smem + OFF_HQ);
  float* gb = (float*)(smem + OFF_G) + w * (16*RPAD);
  float* ob = out + (size_t)b * CN*HN*WN;

  #pragma unroll 1
  for (int i = 0; i < 8; i++){
    int gy = 4*w + (i >> 1);          /* row within tile (0..31) */
    int gx = (i & 1) * 16;            /* column offset of the 16-px group */
    int xA = x0 + gx + gid, xB = xA + 8;
    size_t rowoff = (size_t)(y0 + gy) * WN;

    /* A fragments: lane (gid,tig) computes channel 'tig' feats at px gid, gid+8 */
    float xvA = __ldg(xb + (size_t)tig*HN*WN + rowoff + xA);
    float xvB = __ldg(xb + (size_t)tig*HN*WN + rowoff + xB);
    float sA = hsf[(tig*RH + gy)*RPAD + gx + gid];
    float sB = hsf[(tig*RH + gy)*RPAD + gx + gid + 8];
    float qA = hqf[(tig*RH + gy)*RPAD + gx + gid];
    float qB = hqf[(tig*RH + gy)*RPAD + gx + gid + 8];
    float mA = sA * (1.0f/49.0f), mB = sB * (1.0f/49.0f);
    float msqA = qA * (1.0f/49.0f), msqB = qB * (1.0f/49.0f);
    float vA = fmaxf(fmaf(-mA, mA, msqA), 0.0f);
    float vB = fmaxf(fmaf(-mB, mB, msqB), 0.0f);
    u32 a00 = tf(xvA), a01 = tf(xvB), a02 = tf(mA),   a03 = tf(mB);    /* k-tile 0: x | mean */
    u32 a10 = tf(vA),  a11 = tf(vB),  a12 = tf(msqA), a13 = tf(msqB);  /* k-tile 1: var | msq */

    /* W1 GEMM: h[16px x 32k] */
    float d[4][4];
    #pragma unroll
    for (int nt = 0; nt < 4; nt++){
      d[nt][0]=d[nt][1]=d[nt][2]=d[nt][3]=0.0f;
      mma8(d[nt], a00, a01, a02, a03, w1f[0][nt][0], w1f[0][nt][1]);
      mma8(d[nt], a10, a11, a12, a13, w1f[1][nt][0], w1f[1][nt][1]);
    }

    /* +b1, gelu, stage g to smem [px][n] (rows padded to 36) */
    #pragma unroll
    for (int nt = 0; nt < 4; nt++){
      u64 g0 = gelu2(fadd2(pk(d[nt][0], d[nt][1]), b1p[nt]));
      u64 g1 = gelu2(fadd2(pk(d[nt][2], d[nt][3]), b1p[nt]));
      *(u64*)(gb + gid*RPAD     + nt*8 + 2*tig) = g0;
      *(u64*)(gb + (gid+8)*RPAD + nt*8 + 2*tig) = g1;
    }
    __syncwarp();

    /* W2 GEMM: res[16px x 8(4 valid)] */
    float res[4]; res[0]=res[1]=res[2]=res[3]=0.0f;
    #pragma unroll
    for (int kt = 0; kt < 4; kt++){
      u32 g0 = tf(gb[gid*RPAD     + kt*8 + tig]);
      u32 g1 = tf(gb[(gid+8)*RPAD + kt*8 + tig]);
      u32 g2 = tf(gb[gid*RPAD     + kt*8 + tig + 4]);
      u32 g3 = tf(gb[(gid+8)*RPAD + kt*8 + tig + 4]);
      mma8(res, g0, g1, g2, g3, w2f[kt][0], w2f[kt][1]);
    }
    __syncwarp();

    /* epilogue: lanes tig<2 hold channels {2tig, 2tig+1} */
    if (tig < 2){
      int c0 = 2*tig, c1 = c0 + 1;
      size_t b0o = (size_t)c0*HN*WN + rowoff;
      size_t b1o = (size_t)c1*HN*WN + rowoff;
      ob[b0o + xA] = __ldg(xb + b0o + xA) + b2v0 + res[0];
      ob[b1o + xA] = __ldg(xb + b1o + xA) + b2v1 + res[1];
      ob[b0o + xB] = __ldg(xb + b0o + xB) + b2v0 + res[2];
      ob[b1o + xB] = __ldg(xb + b1o + xB) + b2v1 + res[3];
    }
  }
}

extern "C" void kernel_launch(void* const* d_in, const int* in_sizes, int n_in,
                              void* d_out, int out_size)
{
  const float *x=0, *W1=0, *b1=0, *W2=0, *b2=0;
  for (int i = 0; i < n_in; i++){
    switch (in_sizes[i]){
      case BN*CN*HN*WN: x  = (const float*)d_in[i]; break;
      case HID*4*CN:    W1 = (const float*)d_in[i]; break;
      case HID:         b1 = (const float*)d_in[i]; break;
      case CN*HID:      W2 = (const float*)d_in[i]; break;
      case CN:          b2 = (const float*)d_in[i]; break;
      default: break;
    }
  }
  static int attr_set = 0;
  if (!attr_set){
    cudaFuncSetAttribute(lee_kernel, cudaFuncAttributeMaxDynamicSharedMemorySize, SMEM_TOTAL);
    attr_set = 1;
  }
  dim3 grid(WN/TX, HN/TY, BN);   /* 16 x 16 x 16 */
  lee_kernel<<<grid, 256, SMEM_TOTAL>>>(x, W1, b1, W2, b2, (float*)d_out);
}

// round 15
// speedup vs baseline: 1.2463x; 1.0503x over previous
#include <cuda_runtime.h>
#include <cstdint>
typedef unsigned long long u64;
typedef unsigned int u32;

#define BN 16
#define CN 4
#define HN 512
#define WN 512
#define HID 32
#define TX 32
#define TY 32
#define RAD 3
#define RH 38
#define RPAD 36            /* padded floats per hsp/hqp row (18 u64) */

#define OFF_G  0           /* 8 warps x 16 rows x 36 floats = 18432 B */
#define OFF_HS 18432       /* 4*38*36*4 = 21888 B */
#define OFF_HQ 40320       /* 21888 B */
#define SMEM_TOTAL 62208

#define SGNM 0x8000000080000000ULL

/* ---------------- f32x2 helpers ---------------- */
__device__ __forceinline__ u64 pk(float lo, float hi){ u64 r; asm("mov.b64 %0,{%1,%2};":"=l"(r):"f"(lo),"f"(hi)); return r; }
__device__ __forceinline__ void upk(u64 v,float&lo,float&hi){ asm("mov.b64 {%0,%1},%2;":"=f"(lo),"=f"(hi):"l"(v)); }
__device__ __forceinline__ u64 dup2(float x){ u64 r; asm("mov.b64 %0,{%1,%1};":"=l"(r):"f"(x)); return r; }
__device__ __forceinline__ u64 ffma2(u64 a,u64 b,u64 c){ u64 d; asm("fma.rn.f32x2 %0,%1,%2,%3;":"=l"(d):"l"(a),"l"(b),"l"(c)); return d; }
__device__ __forceinline__ u64 fadd2(u64 a,u64 b){ u64 d; asm("add.rn.f32x2 %0,%1,%2;":"=l"(d):"l"(a),"l"(b)); return d; }
__device__ __forceinline__ u64 fmul2(u64 a,u64 b){ u64 d; asm("mul.rn.f32x2 %0,%1,%2;":"=l"(d):"l"(a),"l"(b)); return d; }
__device__ __forceinline__ float rcpf(float x){ float r; asm("rcp.approx.ftz.f32 %0,%1;":"=f"(r):"f"(x)); return r; }
__device__ __forceinline__ float ex2f(float x){ float r; asm("ex2.approx.ftz.f32 %0,%1;":"=f"(r):"f"(x)); return r; }

/* tanh-form gelu (validated R8) */
__device__ __forceinline__ u64 gelu2(u64 h){
  u64 h2 = fmul2(h, h);
  u64 s  = ffma2(h2, dup2(0.10294456f), dup2(2.3022077f));
  u64 tg = fmul2(h, s);
  float t0,t1; upk(tg,t0,t1);
  u64 E  = pk(ex2f(t0), ex2f(t1));
  u64 dn = fadd2(E, dup2(1.0f));
  float d0,d1; upk(dn,d0,d1);
  u64 r  = pk(rcpf(d0), rcpf(d1));
  u64 m  = fmul2(h, r);
  return fadd2(h, m ^ SGNM);
}
__device__ __forceinline__ int refl(int i, int n){ if (i<0) i=-i; if (i>=n) i=2*n-2-i; return i; }

/* tf32 convert (round-to-nearest) — used ONLY for one-time weight conversion */
__device__ __forceinline__ u32 tf(float f){ u32 r; asm("cvt.rna.tf32.f32 %0, %1;":"=r"(r):"f"(f)); return r; }

/* m16n8k8 tf32 MMA, accumulate in place */
__device__ __forceinline__ void mma8(float* d, u32 a0, u32 a1, u32 a2, u32 a3, u32 b0, u32 b1){
  asm volatile(
    "mma.sync.aligned.m16n8k8.row.col.f32.tf32.tf32.f32 "
    "{%0,%1,%2,%3},{%4,%5,%6,%7},{%8,%9},{%0,%1,%2,%3};"
    : "+f"(d[0]),"+f"(d[1]),"+f"(d[2]),"+f"(d[3])
    : "r"(a0),"r"(a1),"r"(a2),"r"(a3),"r"(b0),"r"(b1));
}

__global__ void __launch_bounds__(256,2)
lee_kernel(const float* __restrict__ x, const float* __restrict__ W1,
           const float* __restrict__ b1, const float* __restrict__ W2,
           const float* __restrict__ b2, float* __restrict__ out)
{
  extern __shared__ __align__(16) char smem[];
  const int tid = threadIdx.x;
  const int w    = tid >> 5;          /* warp 0..7 */
  const int lane = tid & 31;
  const int gid  = lane >> 2;         /* 0..7 */
  const int tig  = lane & 3;          /* 0..3 */
  const int x0 = blockIdx.x * TX;
  const int y0 = blockIdx.y * TY;
  const int b  = blockIdx.z;
  const float* xb = x + (size_t)b * CN * HN * WN;

  /* ---- weight fragments -> registers (once, RNA-rounded) ---- */
  u32 w1f[2][4][2];
  #pragma unroll
  for (int kt = 0; kt < 2; kt++)
    #pragma unroll
    for (int nt = 0; nt < 4; nt++){
      w1f[kt][nt][0] = tf(__ldg(W1 + (nt*8 + gid)*16 + kt*8 + tig));
      w1f[kt][nt][1] = tf(__ldg(W1 + (nt*8 + gid)*16 + kt*8 + tig + 4));
    }
  u32 w2f[4][2];
  #pragma unroll
  for (int kt = 0; kt < 4; kt++){
    w2f[kt][0] = (gid < CN) ? tf(__ldg(W2 + gid*HID + kt*8 + tig))     : 0u;
    w2f[kt][1] = (gid < CN) ? tf(__ldg(W2 + gid*HID + kt*8 + tig + 4)) : 0u;
  }
  u64 b1p[4];
  #pragma unroll
  for (int nt = 0; nt < 4; nt++)
    b1p[nt] = pk(__ldg(b1 + nt*8 + 2*tig), __ldg(b1 + nt*8 + 2*tig + 1));
  float b2v0 = (tig < 2) ? __ldg(b2 + 2*tig)     : 0.0f;
  float b2v1 = (tig < 2) ? __ldg(b2 + 2*tig + 1) : 0.0f;

  u64* hsw = (u64*)(smem + OFF_HS);
  u64* hqw = (u64*)(smem + OFF_HQ);

  /* ---- stage 1: horizontal 7-window running sums (proven; rows padded to 36) ---- */
  const bool ixf = (x0 >= RAD) && (x0 + TX + RAD <= WN);
  for (int t = tid; t < CN*RH*8; t += 256){
    int c = t & 3, g = (t >> 2) & 7, r = t >> 5;
    int gy = refl(y0 - RAD + r, HN);
    const float* row = xb + ((size_t)c*HN + gy) * WN;
    int base = x0 + 4*g - RAD;
    float v[10];
    if (ixf){
      const float4* p = (const float4*)(row + base - 1);
      float4 f0 = __ldg(p), f1 = __ldg(p+1), f2 = __ldg(p+2);
      v[0]=f0.y; v[1]=f0.z; v[2]=f0.w; v[3]=f1.x; v[4]=f1.y;
      v[5]=f1.z; v[6]=f1.w; v[7]=f2.x; v[8]=f2.y; v[9]=f2.z;
    } else {
      #pragma unroll
      for (int d = 0; d < 10; d++) v[d] = __ldg(row + refl(base + d, WN));
    }
    float s0 = ((v[0]+v[1])+(v[2]+v[3])) + ((v[4]+v[5])+v[6]);
    float s1 = s0 + (v[7]-v[0]);
    float s2 = s1 + (v[8]-v[1]);
    float s3 = s2 + (v[9]-v[2]);
    float q[10];
    #pragma unroll
    for (int d = 0; d < 10; d++) q[d] = v[d]*v[d];
    float q0 = ((q[0]+q[1])+(q[2]+q[3])) + ((q[4]+q[5])+q[6]);
    float q1 = q0 + (q[7]-q[0]);
    float q2 = q1 + (q[8]-q[1]);
    float q3 = q2 + (q[9]-q[2]);
    int bi = (c*RH + r)*18 + 2*g;
    hsw[bi]   = pk(s0,s1);  hsw[bi+1] = pk(s2,s3);
    hqw[bi]   = pk(q0,q1);  hqw[bi+1] = pk(q2,q3);
  }
  __syncthreads();

  /* ---- stage 1.5: vertical 7-sums IN PLACE (proven) ---- */
  {
    int c  = tid & 3, px = (tid >> 2) & 15, qy = tid >> 6;
    u64 rs[14], rq[14];
    #pragma unroll
    for (int j = 0; j < 14; j++){
      rs[j] = hsw[(c*RH + 8*qy + j)*18 + px];
      rq[j] = hqw[(c*RH + 8*qy + j)*18 + px];
    }
    __syncthreads();
    u64 s = fadd2(fadd2(fadd2(rs[0],rs[1]), fadd2(rs[2],rs[3])), fadd2(fadd2(rs[4],rs[5]), rs[6]));
    u64 q = fadd2(fadd2(fadd2(rq[0],rq[1]), fadd2(rq[2],rq[3])), fadd2(fadd2(rq[4],rq[5]), rq[6]));
    hsw[(c*RH + 8*qy)*18 + px] = s;
    hqw[(c*RH + 8*qy)*18 + px] = q;
    #pragma unroll
    for (int i = 1; i < 8; i++){
      s = fadd2(s, fadd2(rs[i+6], rs[i-1] ^ SGNM));
      q = fadd2(q, fadd2(rq[i+6], rq[i-1] ^ SGNM));
      hsw[(c*RH + 8*qy + i)*18 + px] = s;
      hqw[(c*RH + 8*qy + i)*18 + px] = q;
    }
  }
  __syncthreads();

  /* ---- stage 2: warp-level tf32 MMA over 16-px groups ---- */
  const float* hsf = (const float*)(smem + OFF_HS);
  const float* hqf = (const float*)(smem + OFF_HQ);
  float* gb = (float*)(smem + OFF_G) + w * (16*RPAD);
  const u32* gbw = (const u32*)gb;
  float* ob = out + (size_t)b * CN*HN*WN;

  #pragma unroll 1
  for (int i = 0; i < 8; i++){
    int gy = 4*w + (i >> 1);          /* row within tile (0..31) */
    int gx = (i & 1) * 16;            /* column offset of the 16-px group */
    int xA = x0 + gx + gid, xB = xA + 8;
    size_t rowoff = (size_t)(y0 + gy) * WN;

    /* A fragments: lane (gid,tig) computes channel 'tig' feats at px gid, gid+8.
       Raw f32 bits feed the MMA (implicit tf32 truncation — within error budget). */
    float xvA = __ldg(xb + (size_t)tig*HN*WN + rowoff + xA);
    float xvB = __ldg(xb + (size_t)tig*HN*WN + rowoff + xB);
    float sA = hsf[(tig*RH + gy)*RPAD + gx + gid];
    float sB = hsf[(tig*RH + gy)*RPAD + gx + gid + 8];
    float qA = hqf[(tig*RH + gy)*RPAD + gx + gid];
    float qB = hqf[(tig*RH + gy)*RPAD + gx + gid + 8];
    float mA = sA * (1.0f/49.0f), mB = sB * (1.0f/49.0f);
    float msqA = qA * (1.0f/49.0f), msqB = qB * (1.0f/49.0f);
    float vA = fmaxf(fmaf(-mA, mA, msqA), 0.0f);
    float vB = fmaxf(fmaf(-mB, mB, msqB), 0.0f);
    u32 a00 = __float_as_uint(xvA), a01 = __float_as_uint(xvB);
    u32 a02 = __float_as_uint(mA),  a03 = __float_as_uint(mB);
    u32 a10 = __float_as_uint(vA),  a11 = __float_as_uint(vB);
    u32 a12 = __float_as_uint(msqA),a13 = __float_as_uint(msqB);

    /* W1 GEMM: h[16px x 32k] */
    float d[4][4];
    #pragma unroll
    for (int nt = 0; nt < 4; nt++){
      d[nt][0]=d[nt][1]=d[nt][2]=d[nt][3]=0.0f;
      mma8(d[nt], a00, a01, a02, a03, w1f[0][nt][0], w1f[0][nt][1]);
      mma8(d[nt], a10, a11, a12, a13, w1f[1][nt][0], w1f[1][nt][1]);
    }

    /* +b1, gelu, stage g to smem [px][n] (rows padded to 36) */
    #pragma unroll
    for (int nt = 0; nt < 4; nt++){
      u64 g0 = gelu2(fadd2(pk(d[nt][0], d[nt][1]), b1p[nt]));
      u64 g1 = gelu2(fadd2(pk(d[nt][2], d[nt][3]), b1p[nt]));
      *(u64*)(gb + gid*RPAD     + nt*8 + 2*tig) = g0;
      *(u64*)(gb + (gid+8)*RPAD + nt*8 + 2*tig) = g1;
    }
    __syncwarp();

    /* W2 GEMM: res[16px x 8(4 valid)]; raw f32 bits as tf32 */
    float res[4]; res[0]=res[1]=res[2]=res[3]=0.0f;
    #pragma unroll
    for (int kt = 0; kt < 4; kt++){
      u32 g0 = gbw[gid*RPAD     + kt*8 + tig];
      u32 g1 = gbw[(gid+8)*RPAD + kt*8 + tig];
      u32 g2 = gbw[gid*RPAD     + kt*8 + tig + 4];
      u32 g3 = gbw[(gid+8)*RPAD + kt*8 + tig + 4];
      mma8(res, g0, g1, g2, g3, w2f[kt][0], w2f[kt][1]);
    }
    __syncwarp();

    /* epilogue: x re-read replaced by intra-warp shfl.
       x(channel c, px gid[+8]) lives in lane (gid<<2)|c as xvA/xvB. */
    int base4 = gid << 2;
    int s0l = base4 | (tig << 1);       /* channel 2*tig   */
    int s1l = s0l | 1;                  /* channel 2*tig+1 */
    float xA0 = __shfl_sync(0xffffffffu, xvA, s0l);
    float xA1 = __shfl_sync(0xffffffffu, xvA, s1l);
    float xB0 = __shfl_sync(0xffffffffu, xvB, s0l);
    float xB1 = __shfl_sync(0xffffffffu, xvB, s1l);
    if (tig < 2){
      int c0 = 2*tig, c1 = c0 + 1;
      size_t b0o = (size_t)c0*HN*WN + rowoff;
      size_t b1o = (size_t)c1*HN*WN + rowoff;
      ob[b0o + xA] = xA0 + b2v0 + res[0];
      ob[b1o + xA] = xA1 + b2v1 + res[1];
      ob[b0o + xB] = xB0 + b2v0 + res[2];
      ob[b1o + xB] = xB1 + b2v1 + res[3];
    }
  }
}

extern "C" void kernel_launch(void* const* d_in, const int* in_sizes, int n_in,
                              void* d_out, int out_size)
{
  const float *x=0, *W1=0, *b1=0, *W2=0, *b2=0;
  for (int i = 0; i < n_in; i++){
    switch (in_sizes[i]){
      case BN*CN*HN*WN: x  = (const float*)d_in[i]; break;
      case HID*4*CN:    W1 = (const float*)d_in[i]; break;
      case HID:         b1 = (const float*)d_in[i]; break;
      case CN*HID:      W2 = (const float*)d_in[i]; break;
      case CN:          b2 = (const float*)d_in[i]; break;
      default: break;
    }
  }
  static int attr_set = 0;
  if (!attr_set){
    cudaFuncSetAttribute(lee_kernel, cudaFuncAttributeMaxDynamicSharedMemorySize, SMEM_TOTAL);
    attr_set = 1;
  }
  dim3 grid(WN/TX, HN/TY, BN);   /* 16 x 16 x 16 */
  lee_kernel<<<grid, 256, SMEM_TOTAL>>>(x, W1, b1, W2, b2, (float*)d_out);
}